// round 3
// baseline (speedup 1.0000x reference)
#include <cuda_runtime.h>
#include <math.h>

#define Bsz 2
#define Sq  2048
#define Dm  1024
#define Hh  16
#define DKh 64
#define Mrows (Bsz*Sq)   // 4096

// Device scratch (allocation-free rule: static __device__ arrays)
__device__ float g_Q[Mrows*Dm];
__device__ float g_K[Mrows*Dm];
__device__ float g_V[Mrows*Dm];
__device__ float g_C[Mrows*Dm];

// ---------------------------------------------------------------------------
// GEMM: out = X[M,K] * W[N,K]^T + bias   (both operands K-contiguous)
// MODE 0: out[m*N + n]                  (plain [B,S,D])
// MODE 1: out[((b*H + h)*S + s)*DK + dk] (per-head [B,H,S,DK] layout)
// M=4096, N=1024, K=1024 fixed. BM=128, BN=64, BK=16, 256 threads, 8x4 microtile
// ---------------------------------------------------------------------------
template<int MODE>
__global__ void __launch_bounds__(256) gemm_kernel(
    const float* __restrict__ X, const float* __restrict__ W,
    const float* __restrict__ bias, float* __restrict__ out)
{
    const int K = Dm, N = Dm;
    __shared__ float As[16][132];  // [k][m], padded
    __shared__ float Bs[16][68];   // [k][n], padded

    const int tid = threadIdx.x;
    const int m0 = blockIdx.y * 128;
    const int n0 = blockIdx.x * 64;
    const int ty = tid >> 4;   // 0..15 -> 8 rows each
    const int tx = tid & 15;   // 0..15 -> 4 cols each

    float acc[8][4];
    #pragma unroll
    for (int i = 0; i < 8; i++)
        #pragma unroll
        for (int j = 0; j < 4; j++) acc[i][j] = 0.0f;

    for (int kt = 0; kt < K; kt += 16) {
        // Load X tile (128x16) transposed into As[k][m]
        #pragma unroll
        for (int i = 0; i < 2; i++) {
            int lin = tid + i * 256;       // 0..511
            int row = lin >> 2;            // 0..127
            int kq  = lin & 3;             // float4 slot in k
            float4 v = *(const float4*)&X[(m0 + row) * K + kt + kq * 4];
            As[kq*4+0][row] = v.x; As[kq*4+1][row] = v.y;
            As[kq*4+2][row] = v.z; As[kq*4+3][row] = v.w;
        }
        // Load W tile (64x16) transposed into Bs[k][n]
        {
            int row = tid >> 2;            // 0..63
            int kq  = tid & 3;
            float4 v = *(const float4*)&W[(n0 + row) * K + kt + kq * 4];
            Bs[kq*4+0][row] = v.x; Bs[kq*4+1][row] = v.y;
            Bs[kq*4+2][row] = v.z; Bs[kq*4+3][row] = v.w;
        }
        __syncthreads();

        #pragma unroll
        for (int k = 0; k < 16; k++) {
            float a[8], b[4];
            float4 a0 = *(const float4*)&As[k][ty * 8];
            float4 a1 = *(const float4*)&As[k][ty * 8 + 4];
            float4 bb = *(const float4*)&Bs[k][tx * 4];
            a[0]=a0.x; a[1]=a0.y; a[2]=a0.z; a[3]=a0.w;
            a[4]=a1.x; a[5]=a1.y; a[6]=a1.z; a[7]=a1.w;
            b[0]=bb.x; b[1]=bb.y; b[2]=bb.z; b[3]=bb.w;
            #pragma unroll
            for (int i = 0; i < 8; i++)
                #pragma unroll
                for (int j = 0; j < 4; j++)
                    acc[i][j] = fmaf(a[i], b[j], acc[i][j]);
        }
        __syncthreads();
    }

    float4 bv = *(const float4*)&bias[n0 + tx * 4];
    #pragma unroll
    for (int r = 0; r < 8; r++) {
        int m = m0 + ty * 8 + r;
        float4 o;
        o.x = acc[r][0] + bv.x; o.y = acc[r][1] + bv.y;
        o.z = acc[r][2] + bv.z; o.w = acc[r][3] + bv.w;
        if (MODE == 0) {
            *(float4*)&out[m * N + n0 + tx * 4] = o;
        } else {
            int n  = n0 + tx * 4;
            int bb = m / Sq, ss = m % Sq;
            int h  = n / DKh, dk = n % DKh;  // n0 is head-aligned (64)
            *(float4*)&out[((bb * Hh + h) * Sq + ss) * DKh + dk] = o;
        }
    }
}

// ---------------------------------------------------------------------------
// Flash attention, fp32. One block handles 64 queries of one (b,h).
// Streams over 32 key tiles of 64. 256 threads.
// smem: Qt[dk][q] (64x68), Kt[dk][k] (64x68), Vs[k][dk] (64x68), Ps[q][k] (64x68)
// ---------------------------------------------------------------------------
#define APAD 68
#define ATT_SMEM (4 * 64 * APAD * 4)

__global__ void __launch_bounds__(256) attn_kernel(
    const float* __restrict__ Qg, const float* __restrict__ Kg,
    const float* __restrict__ Vg, const int* __restrict__ mask,
    float* __restrict__ ctx)
{
    extern __shared__ float sm[];
    float* Qt = sm;
    float* Kt = sm + 64 * APAD;
    float* Vs = sm + 2 * 64 * APAD;
    float* Ps = sm + 3 * 64 * APAD;

    const int tid = threadIdx.x;
    const int bh  = blockIdx.y;
    const int b   = bh >> 4;
    const int h   = bh & 15;
    const int q0  = blockIdx.x * 64;

    const float* Qb = Qg + (size_t)(b * Hh + h) * Sq * DKh;
    const float* Kb = Kg + (size_t)(b * Hh + h) * Sq * DKh;
    const float* Vb = Vg + (size_t)(b * Hh + h) * Sq * DKh;
    const float scale = 0.125f;  // 1/sqrt(64)

    // Load Q tile transposed (dk-major), pre-scaled
    #pragma unroll
    for (int i = 0; i < 4; i++) {
        int lin = tid + i * 256;   // 0..1023
        int qq  = lin >> 4;        // 0..63
        int xx  = lin & 15;        // float4 slot in dk
        float4 v = *(const float4*)&Qb[(q0 + qq) * DKh + xx * 4];
        Qt[(xx*4+0)*APAD + qq] = v.x * scale;
        Qt[(xx*4+1)*APAD + qq] = v.y * scale;
        Qt[(xx*4+2)*APAD + qq] = v.z * scale;
        Qt[(xx*4+3)*APAD + qq] = v.w * scale;
    }

    const int g  = tid >> 4;   // row group 0..15 (4 queries each)
    const int x  = tid & 15;   // col group 0..15 (4 cols each)
    const int qr = g * 4;
    const int cc = x * 4;

    float ctxr[4][4];
    float mrow[4], lrow[4];
    #pragma unroll
    for (int i = 0; i < 4; i++) {
        mrow[i] = -1e30f; lrow[i] = 0.0f;
        #pragma unroll
        for (int j = 0; j < 4; j++) ctxr[i][j] = 0.0f;
    }

    for (int t = 0; t < Sq; t += 64) {
        __syncthreads();  // previous tile's PV reads done
        // Load K (transposed) and V tiles
        #pragma unroll
        for (int i = 0; i < 4; i++) {
            int lin = tid + i * 256;
            int kk  = lin >> 4;
            int xx  = lin & 15;
            float4 kv = *(const float4*)&Kb[(t + kk) * DKh + xx * 4];
            Kt[(xx*4+0)*APAD + kk] = kv.x;
            Kt[(xx*4+1)*APAD + kk] = kv.y;
            Kt[(xx*4+2)*APAD + kk] = kv.z;
            Kt[(xx*4+3)*APAD + kk] = kv.w;
            float4 vv = *(const float4*)&Vb[(t + kk) * DKh + xx * 4];
            *(float4*)&Vs[kk * APAD + xx * 4] = vv;
        }
        __syncthreads();

        // S tile (4x4 per thread): rows qr.., cols cc..
        float s[4][4];
        #pragma unroll
        for (int i = 0; i < 4; i++)
            #pragma unroll
            for (int j = 0; j < 4; j++) s[i][j] = 0.0f;

        #pragma unroll 16
        for (int d = 0; d < 64; d++) {
            float4 aq = *(const float4*)&Qt[d * APAD + qr];
            float4 bk = *(const float4*)&Kt[d * APAD + cc];
            float a[4] = {aq.x, aq.y, aq.z, aq.w};
            float kbv[4] = {bk.x, bk.y, bk.z, bk.w};
            #pragma unroll
            for (int i = 0; i < 4; i++)
                #pragma unroll
                for (int j = 0; j < 4; j++)
                    s[i][j] = fmaf(a[i], kbv[j], s[i][j]);
        }

        // Mask (broadcast over b,h): mask[q_global*S + k_global]
        #pragma unroll
        for (int i = 0; i < 4; i++) {
            int4 mk = *(const int4*)&mask[(size_t)(q0 + qr + i) * Sq + t + cc];
            if (mk.x == 0) s[i][0] = -1e9f;
            if (mk.y == 0) s[i][1] = -1e9f;
            if (mk.z == 0) s[i][2] = -1e9f;
            if (mk.w == 0) s[i][3] = -1e9f;
        }

        // Online softmax per row (16-lane shuffle reduce)
        #pragma unroll
        for (int i = 0; i < 4; i++) {
            float mx = fmaxf(fmaxf(s[i][0], s[i][1]), fmaxf(s[i][2], s[i][3]));
            #pragma unroll
            for (int off = 8; off >= 1; off >>= 1)
                mx = fmaxf(mx, __shfl_xor_sync(0xffffffffu, mx, off));
            float mn = fmaxf(mrow[i], mx);
            float ssum = 0.0f;
            #pragma unroll
            for (int j = 0; j < 4; j++) {
                s[i][j] = __expf(s[i][j] - mn);
                ssum += s[i][j];
            }
            #pragma unroll
            for (int off = 8; off >= 1; off >>= 1)
                ssum += __shfl_xor_sync(0xffffffffu, ssum, off);
            float corr = __expf(mrow[i] - mn);
            lrow[i] = lrow[i] * corr + ssum;
            mrow[i] = mn;
            #pragma unroll
            for (int j = 0; j < 4; j++) ctxr[i][j] *= corr;
            *(float4*)&Ps[(qr + i) * APAD + cc] =
                make_float4(s[i][0], s[i][1], s[i][2], s[i][3]);
        }
        __syncthreads();

        // ctx += P * V  (thread: 4 queries x 4 dk)
        #pragma unroll 8
        for (int j = 0; j < 64; j++) {
            float4 v = *(const float4*)&Vs[j * APAD + cc];
            float p0 = Ps[(qr + 0) * APAD + j];
            float p1 = Ps[(qr + 1) * APAD + j];
            float p2 = Ps[(qr + 2) * APAD + j];
            float p3 = Ps[(qr + 3) * APAD + j];
            ctxr[0][0] = fmaf(p0, v.x, ctxr[0][0]); ctxr[0][1] = fmaf(p0, v.y, ctxr[0][1]);
            ctxr[0][2] = fmaf(p0, v.z, ctxr[0][2]); ctxr[0][3] = fmaf(p0, v.w, ctxr[0][3]);
            ctxr[1][0] = fmaf(p1, v.x, ctxr[1][0]); ctxr[1][1] = fmaf(p1, v.y, ctxr[1][1]);
            ctxr[1][2] = fmaf(p1, v.z, ctxr[1][2]); ctxr[1][3] = fmaf(p1, v.w, ctxr[1][3]);
            ctxr[2][0] = fmaf(p2, v.x, ctxr[2][0]); ctxr[2][1] = fmaf(p2, v.y, ctxr[2][1]);
            ctxr[2][2] = fmaf(p2, v.z, ctxr[2][2]); ctxr[2][3] = fmaf(p2, v.w, ctxr[2][3]);
            ctxr[3][0] = fmaf(p3, v.x, ctxr[3][0]); ctxr[3][1] = fmaf(p3, v.y, ctxr[3][1]);
            ctxr[3][2] = fmaf(p3, v.z, ctxr[3][2]); ctxr[3][3] = fmaf(p3, v.w, ctxr[3][3]);
        }
    }

    // Normalize and write context in [B,S,D] layout (concat of heads)
    #pragma unroll
    for (int i = 0; i < 4; i++) {
        float inv = 1.0f / fmaxf(lrow[i], 1e-20f);
        float4 o;
        o.x = ctxr[i][0] * inv; o.y = ctxr[i][1] * inv;
        o.z = ctxr[i][2] * inv; o.w = ctxr[i][3] * inv;
        *(float4*)&ctx[(size_t)(b * Sq + q0 + qr + i) * Dm + h * DKh + cc] = o;
    }
}

// ---------------------------------------------------------------------------
extern "C" void kernel_launch(void* const* d_in, const int* in_sizes, int n_in,
                              void* d_out, int out_size)
{
    const float* q    = (const float*)d_in[0];
    const float* k    = (const float*)d_in[1];
    const float* v    = (const float*)d_in[2];
    const int*   mask = (const int*)  d_in[3];
    const float* Wq   = (const float*)d_in[4];
    const float* bq   = (const float*)d_in[5];
    const float* Wk   = (const float*)d_in[6];
    const float* bk   = (const float*)d_in[7];
    const float* Wv   = (const float*)d_in[8];
    const float* bv   = (const float*)d_in[9];
    const float* Wo   = (const float*)d_in[10];
    const float* bo   = (const float*)d_in[11];
    float* out = (float*)d_out;

    float *gq, *gk, *gv, *gc;
    cudaGetSymbolAddress((void**)&gq, g_Q);
    cudaGetSymbolAddress((void**)&gk, g_K);
    cudaGetSymbolAddress((void**)&gv, g_V);
    cudaGetSymbolAddress((void**)&gc, g_C);

    dim3 gg(Dm / 64, Mrows / 128);  // (16, 32)

    gemm_kernel<1><<<gg, 256>>>(q, Wq, bq, gq);
    gemm_kernel<1><<<gg, 256>>>(k, Wk, bk, gk);
    gemm_kernel<1><<<gg, 256>>>(v, Wv, bv, gv);

    cudaFuncSetAttribute(attn_kernel,
                         cudaFuncAttributeMaxDynamicSharedMemorySize, ATT_SMEM);
    attn_kernel<<<dim3(Sq / 64, Bsz * Hh), 256, ATT_SMEM>>>(gq, gk, gv, mask, gc);

    gemm_kernel<0><<<gg, 256>>>(gc, Wo, bo, out);
}

// round 4
// speedup vs baseline: 1.1706x; 1.1706x over previous
#include <cuda_runtime.h>

#define Bsz 2
#define Sq  2048
#define Dm  1024
#define Hh  16
#define DKh 64
#define Mrows (Bsz*Sq)   // 4096

// Device scratch (allocation-free rule)
__device__ float g_Q[Mrows*Dm];
__device__ float g_K[Mrows*Dm];
__device__ float g_V[Mrows*Dm];
__device__ float g_C[Mrows*Dm];

// ---------------------------------------------------------------------------
// FFMA-only exp2 (no MUFU). Valid for y <= ~1, clamped below at -120 -> ~0.
// ---------------------------------------------------------------------------
__device__ __forceinline__ float exp2_fast(float y) {
    y = fmaxf(y, -120.0f);
    float t = y + 12582912.0f;                 // round-to-nearest-int magic
    int   n = __float_as_int(t) - 0x4B400000;  // integer part
    float f = y - (t - 12582912.0f);           // fractional part in [-0.5,0.5]
    float p =             1.3333558146e-3f;
    p = fmaf(p, f,        9.6181291076e-3f);
    p = fmaf(p, f,        5.5504108664e-2f);
    p = fmaf(p, f,        2.4022650696e-1f);
    p = fmaf(p, f,        6.9314718056e-1f);
    p = fmaf(p, f,        1.0f);
    return __int_as_float(__float_as_int(p) + (n << 23));
}

// ---------------------------------------------------------------------------
// GEMM: out = X[M,K] * W[N,K]^T + bias. 128x128 tile, BK=16, 256 thr, 8x8 micro
// (split 4+4 rows/cols for conflict-free LDS.128), double-buffered smem.
// MODE 0: out[m*N+n]; MODE 1: out in [B,H,S,DK]
// ---------------------------------------------------------------------------
template<int MODE>
__device__ __forceinline__ void gemm_body(
    const float* __restrict__ X, const float* __restrict__ W,
    const float* __restrict__ bias, float* __restrict__ out)
{
    __shared__ float As[2][16][132];
    __shared__ float Bs[2][16][132];

    const int tid = threadIdx.x;
    const int m0 = blockIdx.y * 128;
    const int n0 = blockIdx.x * 128;
    const int ty = tid >> 4;    // 0..15
    const int tx = tid & 15;    // 0..15

    // load indices (2 float4 each for A and B)
    int rowA[2], c4A[2];
    #pragma unroll
    for (int ii = 0; ii < 2; ii++) {
        int idx = tid + ii * 256;
        rowA[ii] = idx >> 2;
        c4A[ii]  = idx & 3;
    }

    float acc[2][2][4][4];
    #pragma unroll
    for (int a = 0; a < 2; a++)
        #pragma unroll
        for (int b = 0; b < 2; b++)
            #pragma unroll
            for (int i = 0; i < 4; i++)
                #pragma unroll
                for (int j = 0; j < 4; j++) acc[a][b][i][j] = 0.0f;

    float4 pa[2], pb[2];
    // preload kt=0
    #pragma unroll
    for (int ii = 0; ii < 2; ii++) {
        pa[ii] = *(const float4*)&X[(m0 + rowA[ii]) * Dm + c4A[ii] * 4];
        pb[ii] = *(const float4*)&W[(n0 + rowA[ii]) * Dm + c4A[ii] * 4];
    }
    #pragma unroll
    for (int ii = 0; ii < 2; ii++) {
        int r = rowA[ii], c = c4A[ii] * 4;
        As[0][c+0][r] = pa[ii].x; As[0][c+1][r] = pa[ii].y;
        As[0][c+2][r] = pa[ii].z; As[0][c+3][r] = pa[ii].w;
        Bs[0][c+0][r] = pb[ii].x; Bs[0][c+1][r] = pb[ii].y;
        Bs[0][c+2][r] = pb[ii].z; Bs[0][c+3][r] = pb[ii].w;
    }
    __syncthreads();

    for (int kt = 0; kt < 64; kt++) {
        int cur = kt & 1;
        if (kt < 63) {
            #pragma unroll
            for (int ii = 0; ii < 2; ii++) {
                pa[ii] = *(const float4*)&X[(m0 + rowA[ii]) * Dm + (kt+1)*16 + c4A[ii]*4];
                pb[ii] = *(const float4*)&W[(n0 + rowA[ii]) * Dm + (kt+1)*16 + c4A[ii]*4];
            }
        }
        #pragma unroll
        for (int k = 0; k < 16; k++) {
            float4 a0 = *(const float4*)&As[cur][k][ty*4];
            float4 a1 = *(const float4*)&As[cur][k][64 + ty*4];
            float4 b0 = *(const float4*)&Bs[cur][k][tx*4];
            float4 b1 = *(const float4*)&Bs[cur][k][64 + tx*4];
            float af[2][4] = {{a0.x,a0.y,a0.z,a0.w},{a1.x,a1.y,a1.z,a1.w}};
            float bf[2][4] = {{b0.x,b0.y,b0.z,b0.w},{b1.x,b1.y,b1.z,b1.w}};
            #pragma unroll
            for (int a = 0; a < 2; a++)
                #pragma unroll
                for (int b = 0; b < 2; b++)
                    #pragma unroll
                    for (int i = 0; i < 4; i++)
                        #pragma unroll
                        for (int j = 0; j < 4; j++)
                            acc[a][b][i][j] = fmaf(af[a][i], bf[b][j], acc[a][b][i][j]);
        }
        if (kt < 63) {
            int nxt = cur ^ 1;
            #pragma unroll
            for (int ii = 0; ii < 2; ii++) {
                int r = rowA[ii], c = c4A[ii] * 4;
                As[nxt][c+0][r] = pa[ii].x; As[nxt][c+1][r] = pa[ii].y;
                As[nxt][c+2][r] = pa[ii].z; As[nxt][c+3][r] = pa[ii].w;
                Bs[nxt][c+0][r] = pb[ii].x; Bs[nxt][c+1][r] = pb[ii].y;
                Bs[nxt][c+2][r] = pb[ii].z; Bs[nxt][c+3][r] = pb[ii].w;
            }
        }
        __syncthreads();
    }

    float4 bv[2];
    bv[0] = *(const float4*)&bias[n0 + tx*4];
    bv[1] = *(const float4*)&bias[n0 + 64 + tx*4];
    #pragma unroll
    for (int ra = 0; ra < 2; ra++)
        #pragma unroll
        for (int i = 0; i < 4; i++) {
            int m = m0 + ra*64 + ty*4 + i;
            #pragma unroll
            for (int cb = 0; cb < 2; cb++) {
                float4 o;
                float* bvp = (float*)&bv[cb];
                o.x = acc[ra][cb][i][0] + bvp[0];
                o.y = acc[ra][cb][i][1] + bvp[1];
                o.z = acc[ra][cb][i][2] + bvp[2];
                o.w = acc[ra][cb][i][3] + bvp[3];
                int n = n0 + cb*64 + tx*4;
                if (MODE == 0) {
                    *(float4*)&out[m * Dm + n] = o;
                } else {
                    int bb = m >> 11, ss = m & 2047;
                    int h = n >> 6, dk = n & 63;
                    *(float4*)&out[((bb * Hh + h) * Sq + ss) * DKh + dk] = o;
                }
            }
        }
}

__global__ void __launch_bounds__(256, 2) gemm_qkv_kernel(
    const float* __restrict__ q, const float* __restrict__ k, const float* __restrict__ v,
    const float* __restrict__ Wq, const float* __restrict__ Wk, const float* __restrict__ Wv,
    const float* __restrict__ bq, const float* __restrict__ bk, const float* __restrict__ bv,
    float* __restrict__ oq, float* __restrict__ ok, float* __restrict__ ov)
{
    int z = blockIdx.z;
    const float* X = (z == 0) ? q  : (z == 1) ? k  : v;
    const float* W = (z == 0) ? Wq : (z == 1) ? Wk : Wv;
    const float* B = (z == 0) ? bq : (z == 1) ? bk : bv;
    float*       O = (z == 0) ? oq : (z == 1) ? ok : ov;
    gemm_body<1>(X, W, B, O);
}

__global__ void __launch_bounds__(256, 2) gemm_o_kernel(
    const float* __restrict__ X, const float* __restrict__ W,
    const float* __restrict__ bias, float* __restrict__ out)
{
    gemm_body<0>(X, W, bias, out);
}

// ---------------------------------------------------------------------------
// Flash attention fp32, base-2 softmax (no MUFU). 128q x 128k tiles, 256 thr,
// 8x8 microtile (split 4+4). smem: Qt/Kt dk-major [64][132], Vs [128][68],
// Ps [128][132].
// ---------------------------------------------------------------------------
#define PADQ 132
#define PADV 68
#define PADP 132
#define ATT_SMEM ((64*PADQ + 64*PADQ + 128*PADV + 128*PADP) * 4)

__global__ void __launch_bounds__(256, 1) attn_kernel(
    const float* __restrict__ Qg, const float* __restrict__ Kg,
    const float* __restrict__ Vg, const int* __restrict__ mask,
    float* __restrict__ ctxg)
{
    extern __shared__ float sm[];
    float* Qt = sm;                       // [64][132]  (dk, q)
    float* Kt = Qt + 64 * PADQ;           // [64][132]  (dk, k)
    float* Vs = Kt + 64 * PADQ;           // [128][68]  (k, dk)
    float* Ps = Vs + 128 * PADV;          // [128][132] (q, k)

    const int tid = threadIdx.x;
    const int bh  = blockIdx.y;
    const int b   = bh >> 4;
    const int h   = bh & 15;
    const int q0  = blockIdx.x * 128;

    const float* Qb = Qg + (size_t)(b * Hh + h) * Sq * DKh;
    const float* Kb = Kg + (size_t)(b * Hh + h) * Sq * DKh;
    const float* Vb = Vg + (size_t)(b * Hh + h) * Sq * DKh;

    const float QSCALE = 0.125f * 1.44269504f;  // 1/sqrt(64) * log2(e)

    // Load Q tile transposed (dk-major), pre-scaled into base-2 domain
    #pragma unroll
    for (int i = 0; i < 8; i++) {
        int lin = tid + i * 256;     // 0..2047
        int qq  = lin >> 4;          // 0..127
        int x4  = lin & 15;          // dk float4 slot
        float4 v = *(const float4*)&Qb[(q0 + qq) * DKh + x4 * 4];
        Qt[(x4*4+0)*PADQ + qq] = v.x * QSCALE;
        Qt[(x4*4+1)*PADQ + qq] = v.y * QSCALE;
        Qt[(x4*4+2)*PADQ + qq] = v.z * QSCALE;
        Qt[(x4*4+3)*PADQ + qq] = v.w * QSCALE;
    }

    const int g = tid >> 4;     // 0..15 row group
    const int x = tid & 15;     // 0..15 col group
    const int r0l = g * 4;      // local row base (plus +64 for second group)
    const int c0l = x * 4;      // local col base (plus +64 for second group)

    float ctx[2][4][4];
    float mrow[2][4], lrow[2][4], corr[2][4];
    #pragma unroll
    for (int a = 0; a < 2; a++)
        #pragma unroll
        for (int i = 0; i < 4; i++) {
            mrow[a][i] = -1e30f; lrow[a][i] = 0.0f;
            #pragma unroll
            for (int j = 0; j < 4; j++) ctx[a][i][j] = 0.0f;
        }

    for (int t = 0; t < Sq; t += 128) {
        __syncthreads();   // previous PV reads of Vs/Ps complete
        // Load K (transposed to dk-major) and V tiles
        #pragma unroll
        for (int i = 0; i < 8; i++) {
            int lin = tid + i * 256;
            int kk  = lin >> 4;
            int x4  = lin & 15;
            float4 kv = *(const float4*)&Kb[(t + kk) * DKh + x4 * 4];
            Kt[(x4*4+0)*PADQ + kk] = kv.x;
            Kt[(x4*4+1)*PADQ + kk] = kv.y;
            Kt[(x4*4+2)*PADQ + kk] = kv.z;
            Kt[(x4*4+3)*PADQ + kk] = kv.w;
            float4 vv = *(const float4*)&Vb[(t + kk) * DKh + x4 * 4];
            *(float4*)&Vs[kk * PADV + x4 * 4] = vv;
        }
        __syncthreads();

        // ---- S = Q*K^T tile (per thread 8x8 split 4+4) ----
        float s[2][2][4][4];
        #pragma unroll
        for (int a = 0; a < 2; a++)
            #pragma unroll
            for (int c = 0; c < 2; c++)
                #pragma unroll
                for (int i = 0; i < 4; i++)
                    #pragma unroll
                    for (int j = 0; j < 4; j++) s[a][c][i][j] = 0.0f;

        #pragma unroll 4
        for (int d = 0; d < 64; d++) {
            const float* qrow = &Qt[d * PADQ];
            const float* krow = &Kt[d * PADQ];
            float4 a0 = *(const float4*)&qrow[r0l];
            float4 a1 = *(const float4*)&qrow[64 + r0l];
            float4 b0 = *(const float4*)&krow[c0l];
            float4 b1 = *(const float4*)&krow[64 + c0l];
            float af[2][4] = {{a0.x,a0.y,a0.z,a0.w},{a1.x,a1.y,a1.z,a1.w}};
            float bf[2][4] = {{b0.x,b0.y,b0.z,b0.w},{b1.x,b1.y,b1.z,b1.w}};
            #pragma unroll
            for (int a = 0; a < 2; a++)
                #pragma unroll
                for (int c = 0; c < 2; c++)
                    #pragma unroll
                    for (int i = 0; i < 4; i++)
                        #pragma unroll
                        for (int j = 0; j < 4; j++)
                            s[a][c][i][j] = fmaf(af[a][i], bf[c][j], s[a][c][i][j]);
        }

        // ---- mask ----
        #pragma unroll
        for (int a = 0; a < 2; a++)
            #pragma unroll
            for (int i = 0; i < 4; i++) {
                int rg = q0 + a*64 + r0l + i;
                #pragma unroll
                for (int c = 0; c < 2; c++) {
                    int4 mk = *(const int4*)&mask[(size_t)rg * Sq + t + c*64 + c0l];
                    if (mk.x == 0) s[a][c][i][0] = -1e9f;
                    if (mk.y == 0) s[a][c][i][1] = -1e9f;
                    if (mk.z == 0) s[a][c][i][2] = -1e9f;
                    if (mk.w == 0) s[a][c][i][3] = -1e9f;
                }
            }

        // ---- online softmax (base 2), write P to smem ----
        #pragma unroll
        for (int a = 0; a < 2; a++)
            #pragma unroll
            for (int i = 0; i < 4; i++) {
                float mx = s[a][0][i][0];
                #pragma unroll
                for (int j = 1; j < 4; j++) mx = fmaxf(mx, s[a][0][i][j]);
                #pragma unroll
                for (int j = 0; j < 4; j++) mx = fmaxf(mx, s[a][1][i][j]);
                #pragma unroll
                for (int off = 8; off >= 1; off >>= 1)
                    mx = fmaxf(mx, __shfl_xor_sync(0xffffffffu, mx, off));
                float mn = fmaxf(mrow[a][i], mx);
                float ssum = 0.0f;
                #pragma unroll
                for (int c = 0; c < 2; c++)
                    #pragma unroll
                    for (int j = 0; j < 4; j++) {
                        float e = exp2_fast(s[a][c][i][j] - mn);
                        s[a][c][i][j] = e;
                        ssum += e;
                    }
                #pragma unroll
                for (int off = 8; off >= 1; off >>= 1)
                    ssum += __shfl_xor_sync(0xffffffffu, ssum, off);
                float cf = exp2_fast(mrow[a][i] - mn);
                lrow[a][i] = lrow[a][i] * cf + ssum;
                mrow[a][i] = mn;
                corr[a][i] = cf;
                int row = a*64 + r0l + i;
                *(float4*)&Ps[row * PADP + c0l] =
                    make_float4(s[a][0][i][0], s[a][0][i][1], s[a][0][i][2], s[a][0][i][3]);
                *(float4*)&Ps[row * PADP + 64 + c0l] =
                    make_float4(s[a][1][i][0], s[a][1][i][1], s[a][1][i][2], s[a][1][i][3]);
            }
        __syncthreads();

        // ---- ctx = ctx*corr + P*V (thread: 8 rows x 4 dk cols) ----
        #pragma unroll
        for (int a = 0; a < 2; a++)
            #pragma unroll
            for (int i = 0; i < 4; i++)
                #pragma unroll
                for (int j = 0; j < 4; j++) ctx[a][i][j] *= corr[a][i];

        #pragma unroll 2
        for (int j0 = 0; j0 < 128; j0 += 4) {
            float4 p[2][4];
            #pragma unroll
            for (int a = 0; a < 2; a++)
                #pragma unroll
                for (int i = 0; i < 4; i++)
                    p[a][i] = *(const float4*)&Ps[(a*64 + r0l + i) * PADP + j0];
            float4 v0 = *(const float4*)&Vs[(j0+0) * PADV + c0l];
            float4 v1 = *(const float4*)&Vs[(j0+1) * PADV + c0l];
            float4 v2 = *(const float4*)&Vs[(j0+2) * PADV + c0l];
            float4 v3 = *(const float4*)&Vs[(j0+3) * PADV + c0l];
            #pragma unroll
            for (int a = 0; a < 2; a++)
                #pragma unroll
                for (int i = 0; i < 4; i++) {
                    float* pp = (float*)&p[a][i];
                    float* cx = ctx[a][i];
                    cx[0] = fmaf(pp[0], v0.x, cx[0]); cx[1] = fmaf(pp[0], v0.y, cx[1]);
                    cx[2] = fmaf(pp[0], v0.z, cx[2]); cx[3] = fmaf(pp[0], v0.w, cx[3]);
                    cx[0] = fmaf(pp[1], v1.x, cx[0]); cx[1] = fmaf(pp[1], v1.y, cx[1]);
                    cx[2] = fmaf(pp[1], v1.z, cx[2]); cx[3] = fmaf(pp[1], v1.w, cx[3]);
                    cx[0] = fmaf(pp[2], v2.x, cx[0]); cx[1] = fmaf(pp[2], v2.y, cx[1]);
                    cx[2] = fmaf(pp[2], v2.z, cx[2]); cx[3] = fmaf(pp[2], v2.w, cx[3]);
                    cx[0] = fmaf(pp[3], v3.x, cx[0]); cx[1] = fmaf(pp[3], v3.y, cx[1]);
                    cx[2] = fmaf(pp[3], v3.z, cx[2]); cx[3] = fmaf(pp[3], v3.w, cx[3]);
                }
        }
    }

    // ---- normalize + write [B,S,D] ----
    #pragma unroll
    for (int a = 0; a < 2; a++)
        #pragma unroll
        for (int i = 0; i < 4; i++) {
            float inv = 1.0f / fmaxf(lrow[a][i], 1e-20f);
            int row = q0 + a*64 + r0l + i;
            float4 o;
            o.x = ctx[a][i][0] * inv; o.y = ctx[a][i][1] * inv;
            o.z = ctx[a][i][2] * inv; o.w = ctx[a][i][3] * inv;
            *(float4*)&ctxg[(size_t)(b * Sq + row) * Dm + h * DKh + c0l] = o;
        }
}

// ---------------------------------------------------------------------------
extern "C" void kernel_launch(void* const* d_in, const int* in_sizes, int n_in,
                              void* d_out, int out_size)
{
    const float* q    = (const float*)d_in[0];
    const float* k    = (const float*)d_in[1];
    const float* v    = (const float*)d_in[2];
    const int*   mask = (const int*)  d_in[3];
    const float* Wq   = (const float*)d_in[4];
    const float* bq   = (const float*)d_in[5];
    const float* Wk   = (const float*)d_in[6];
    const float* bk   = (const float*)d_in[7];
    const float* Wv   = (const float*)d_in[8];
    const float* bv   = (const float*)d_in[9];
    const float* Wo   = (const float*)d_in[10];
    const float* bo   = (const float*)d_in[11];
    float* out = (float*)d_out;

    float *gq, *gk, *gv, *gc;
    cudaGetSymbolAddress((void**)&gq, g_Q);
    cudaGetSymbolAddress((void**)&gk, g_K);
    cudaGetSymbolAddress((void**)&gv, g_V);
    cudaGetSymbolAddress((void**)&gc, g_C);

    gemm_qkv_kernel<<<dim3(8, 32, 3), 256>>>(q, k, v, Wq, Wk, Wv, bq, bk, bv,
                                             gq, gk, gv);

    static int smem_set = 0;
    if (!smem_set) {
        cudaFuncSetAttribute(attn_kernel,
                             cudaFuncAttributeMaxDynamicSharedMemorySize, ATT_SMEM);
        smem_set = 1;
    }
    attn_kernel<<<dim3(Sq / 128, Bsz * Hh), 256, ATT_SMEM>>>(gq, gk, gv, mask, gc);

    gemm_o_kernel<<<dim3(8, 32), 256>>>(gc, Wo, bo, out);
}

// round 16
// speedup vs baseline: 1.4005x; 1.1964x over previous
#include <cuda_runtime.h>
#include <cstdint>

#define Bsz 2
#define Sq  2048
#define Dm  1024
#define Hh  16
#define DKh 64
#define Mrows (Bsz*Sq)   // 4096

// Device scratch (allocation-free rule)
__device__ float g_Q[Mrows*Dm];
__device__ float g_K[Mrows*Dm];
__device__ float g_V[Mrows*Dm];
__device__ float g_C[Mrows*Dm];

// ===========================================================================
// Helpers: mma.sync (base-target PTX, no sm_103a-only instructions!)
// ===========================================================================
__device__ __forceinline__ uint32_t smem_u32(const void* p) {
    uint32_t a;
    asm("{ .reg .u64 t; cvta.to.shared.u64 t, %1; cvt.u32.u64 %0, t; }"
        : "=r"(a) : "l"(p));
    return a;
}

__device__ __forceinline__ void ldsm_x4(uint32_t& r0, uint32_t& r1,
                                        uint32_t& r2, uint32_t& r3, uint32_t addr) {
    asm volatile("ldmatrix.sync.aligned.m8n8.x4.shared.b16 {%0,%1,%2,%3}, [%4];"
                 : "=r"(r0), "=r"(r1), "=r"(r2), "=r"(r3) : "r"(addr));
}
__device__ __forceinline__ void ldsm_x2(uint32_t& r0, uint32_t& r1, uint32_t addr) {
    asm volatile("ldmatrix.sync.aligned.m8n8.x2.shared.b16 {%0,%1}, [%2];"
                 : "=r"(r0), "=r"(r1) : "r"(addr));
}

__device__ __forceinline__ void mma16816(float* d, const uint32_t* a, const uint32_t* b) {
    asm volatile(
        "mma.sync.aligned.m16n8k16.row.col.f32.bf16.bf16.f32 "
        "{%0,%1,%2,%3}, {%4,%5,%6,%7}, {%8,%9}, {%0,%1,%2,%3};"
        : "+f"(d[0]), "+f"(d[1]), "+f"(d[2]), "+f"(d[3])
        : "r"(a[0]), "r"(a[1]), "r"(a[2]), "r"(a[3]), "r"(b[0]), "r"(b[1]));
}

// fp32 <-> bf16 split helpers (round-to-nearest-even)
__device__ __forceinline__ uint32_t f2bf(float x) {
    uint32_t u = __float_as_uint(x);
    return (u + 0x7FFFu + ((u >> 16) & 1u)) >> 16;
}
__device__ __forceinline__ float bf2f(uint32_t b) {
    return __uint_as_float(b << 16);
}

// ===========================================================================
// mma.sync GEMM: out = X[4096,1024] * W[1024,1024]^T + bias
// 128x128 CTA tile, K chunks of 64, bf16 split (hi*hi + hi*lo + lo*hi).
// 8 warps in 2(M)x4(N) grid; warp tile 64x32; m16n8k16 fragments via ldmatrix.
// MODE 0: out[m*Dm+n]; MODE 1: out in [B,H,S,DK]
// ===========================================================================
#define BROW 72                      // padded row length in bf16 (64 + 8)
#define OFF_AH 0
#define OFF_AL (128*BROW*2)          // 18432 B
#define OFF_BH (2*128*BROW*2)        // 36864
#define OFF_BL (3*128*BROW*2)        // 55296
#define GEMM_SMEM (4*128*BROW*2)     // 73728

template<int MODE>
__device__ __forceinline__ void mma_gemm_body(
    const float* __restrict__ X, const float* __restrict__ W,
    const float* __restrict__ bias, float* __restrict__ out)
{
    extern __shared__ char smem[];
    const uint32_t sb = smem_u32(smem);
    const int tid = threadIdx.x;
    const int wid = tid >> 5;
    const int lane = tid & 31;
    const int warp_m = wid >> 2;     // 0..1  (64 rows each)
    const int warp_n = wid & 3;      // 0..3  (32 cols each)
    const int m0 = blockIdx.y * 128;
    const int n0 = blockIdx.x * 128;

    float acc[4][4][4];
    #pragma unroll
    for (int mi = 0; mi < 4; mi++)
        #pragma unroll
        for (int ni = 0; ni < 4; ni++)
            #pragma unroll
            for (int d = 0; d < 4; d++) acc[mi][ni][d] = 0.0f;

    // ldmatrix lane address components (constant across chunks)
    const int a_row = warp_m * 64 + (lane & 15);
    const int a_khalf = (lane >> 4) << 3;            // 0 or 8
    const int b_row = warp_n * 32 + (lane & 7);
    const int b_khalf = (lane & 8);                  // 0 or 8

    for (int kt = 0; kt < 16; kt++) {
        // ---- load + convert X/W chunk (128x64 fp32 each) into bf16 hi/lo smem ----
        #pragma unroll
        for (int t = 0; t < 8; t++) {
            int idx = tid + t * 256;
            int row = idx >> 4;          // 0..127
            int c4  = idx & 15;          // float4 slot (16 per row)
            uint32_t boff = (uint32_t)(row * BROW + c4 * 4) * 2;  // byte offset

            float4 va = *(const float4*)&X[(size_t)(m0 + row) * Dm + kt * 64 + c4 * 4];
            uint32_t h0 = f2bf(va.x), h1 = f2bf(va.y), h2 = f2bf(va.z), h3 = f2bf(va.w);
            uint32_t l0 = f2bf(va.x - bf2f(h0)), l1 = f2bf(va.y - bf2f(h1));
            uint32_t l2 = f2bf(va.z - bf2f(h2)), l3 = f2bf(va.w - bf2f(h3));
            *(uint2*)(smem + OFF_AH + boff) = make_uint2(h0 | (h1 << 16), h2 | (h3 << 16));
            *(uint2*)(smem + OFF_AL + boff) = make_uint2(l0 | (l1 << 16), l2 | (l3 << 16));

            float4 vb = *(const float4*)&W[(size_t)(n0 + row) * Dm + kt * 64 + c4 * 4];
            h0 = f2bf(vb.x); h1 = f2bf(vb.y); h2 = f2bf(vb.z); h3 = f2bf(vb.w);
            l0 = f2bf(vb.x - bf2f(h0)); l1 = f2bf(vb.y - bf2f(h1));
            l2 = f2bf(vb.z - bf2f(h2)); l3 = f2bf(vb.w - bf2f(h3));
            *(uint2*)(smem + OFF_BH + boff) = make_uint2(h0 | (h1 << 16), h2 | (h3 << 16));
            *(uint2*)(smem + OFF_BL + boff) = make_uint2(l0 | (l1 << 16), l2 | (l3 << 16));
        }
        __syncthreads();

        // ---- compute: 4 k-steps of 16 ----
        #pragma unroll
        for (int ks = 0; ks < 4; ks++) {
            uint32_t bh[4][2], bl[4][2];
            #pragma unroll
            for (int ni = 0; ni < 4; ni++) {
                uint32_t bb = (uint32_t)((b_row + ni * 8) * BROW + ks * 16 + b_khalf) * 2;
                ldsm_x2(bh[ni][0], bh[ni][1], sb + OFF_BH + bb);
                ldsm_x2(bl[ni][0], bl[ni][1], sb + OFF_BL + bb);
            }
            #pragma unroll
            for (int mi = 0; mi < 4; mi++) {
                uint32_t ah[4], al[4];
                uint32_t ab = (uint32_t)((a_row + mi * 16) * BROW + ks * 16 + a_khalf) * 2;
                ldsm_x4(ah[0], ah[1], ah[2], ah[3], sb + OFF_AH + ab);
                ldsm_x4(al[0], al[1], al[2], al[3], sb + OFF_AL + ab);
                #pragma unroll
                for (int ni = 0; ni < 4; ni++) {
                    mma16816(acc[mi][ni], ah, bh[ni]);
                    mma16816(acc[mi][ni], ah, bl[ni]);
                    mma16816(acc[mi][ni], al, bh[ni]);
                }
            }
        }
        __syncthreads();
    }

    // ---- epilogue: D fragment layout m16n8 ----
    #pragma unroll
    for (int mi = 0; mi < 4; mi++) {
        int m_base = m0 + warp_m * 64 + mi * 16 + (lane >> 2);
        #pragma unroll
        for (int ni = 0; ni < 4; ni++) {
            int n = n0 + warp_n * 32 + ni * 8 + (lane & 3) * 2;
            float b0 = bias[n], b1 = bias[n + 1];
            float2 o0 = make_float2(acc[mi][ni][0] + b0, acc[mi][ni][1] + b1);
            float2 o1 = make_float2(acc[mi][ni][2] + b0, acc[mi][ni][3] + b1);
            if (MODE == 0) {
                *(float2*)&out[(size_t)m_base * Dm + n] = o0;
                *(float2*)&out[(size_t)(m_base + 8) * Dm + n] = o1;
            } else {
                int h = n >> 6, dk = n & 63;
                int bb0 = m_base >> 11, ss0 = m_base & 2047;
                *(float2*)&out[((size_t)(bb0 * Hh + h) * Sq + ss0) * DKh + dk] = o0;
                int m1 = m_base + 8;
                int bb1 = m1 >> 11, ss1 = m1 & 2047;
                *(float2*)&out[((size_t)(bb1 * Hh + h) * Sq + ss1) * DKh + dk] = o1;
            }
        }
    }
}

__global__ void __launch_bounds__(256, 2) mma_gemm_qkv(
    const float* __restrict__ q, const float* __restrict__ k, const float* __restrict__ v,
    const float* __restrict__ Wq, const float* __restrict__ Wk, const float* __restrict__ Wv,
    const float* __restrict__ bq, const float* __restrict__ bk, const float* __restrict__ bv,
    float* __restrict__ oq, float* __restrict__ ok, float* __restrict__ ov)
{
    int z = blockIdx.z;
    const float* X = (z == 0) ? q  : (z == 1) ? k  : v;
    const float* W = (z == 0) ? Wq : (z == 1) ? Wk : Wv;
    const float* B = (z == 0) ? bq : (z == 1) ? bk : bv;
    float*       O = (z == 0) ? oq : (z == 1) ? ok : ov;
    mma_gemm_body<1>(X, W, B, O);
}

__global__ void __launch_bounds__(256, 2) mma_gemm_o(
    const float* __restrict__ X, const float* __restrict__ W,
    const float* __restrict__ bias, float* __restrict__ out)
{
    mma_gemm_body<0>(X, W, bias, out);
}

// ===========================================================================
// FFMA-only exp2 (no MUFU)
// ===========================================================================
__device__ __forceinline__ float exp2_fast(float y) {
    y = fmaxf(y, -120.0f);
    float t = y + 12582912.0f;
    int   n = __float_as_int(t) - 0x4B400000;
    float f = y - (t - 12582912.0f);
    float p =             1.3333558146e-3f;
    p = fmaf(p, f,        9.6181291076e-3f);
    p = fmaf(p, f,        5.5504108664e-2f);
    p = fmaf(p, f,        2.4022650696e-1f);
    p = fmaf(p, f,        6.9314718056e-1f);
    p = fmaf(p, f,        1.0f);
    return __int_as_float(__float_as_int(p) + (n << 23));
}

// ===========================================================================
// Flash attention fp32, base-2 softmax. 128q x 64k tiles, 256 thr,
// 8x4 microtile. smem 103 KB -> 2 CTAs/SM.
// ===========================================================================
#define PADQ 132
#define PADK 68
#define ATT_SMEM ((64*PADQ + 64*PADK + 64*PADK + 128*PADK) * 4)  // 103424

__global__ void __launch_bounds__(256, 2) attn_kernel(
    const float* __restrict__ Qg, const float* __restrict__ Kg,
    const float* __restrict__ Vg, const int* __restrict__ mask,
    float* __restrict__ ctxg)
{
    extern __shared__ float smf[];
    float* Qt = smf;                      // [64][132]  (dk, q)
    float* Kt = Qt + 64 * PADQ;           // [64][68]   (dk, k)
    float* Vs = Kt + 64 * PADK;           // [64][68]   (k, dk)
    float* Ps = Vs + 64 * PADK;           // [128][68]  (q, k)

    const int tid = threadIdx.x;
    const int bh  = blockIdx.y;
    const int b   = bh >> 4;
    const int h   = bh & 15;
    const int q0  = blockIdx.x * 128;

    const float* Qb = Qg + (size_t)(b * Hh + h) * Sq * DKh;
    const float* Kb = Kg + (size_t)(b * Hh + h) * Sq * DKh;
    const float* Vb = Vg + (size_t)(b * Hh + h) * Sq * DKh;

    const float QSCALE = 0.125f * 1.44269504f;  // 1/sqrt(64) * log2(e)

    #pragma unroll
    for (int i = 0; i < 8; i++) {
        int lin = tid + i * 256;
        int qq  = lin >> 4;
        int x4  = lin & 15;
        float4 v = *(const float4*)&Qb[(q0 + qq) * DKh + x4 * 4];
        Qt[(x4*4+0)*PADQ + qq] = v.x * QSCALE;
        Qt[(x4*4+1)*PADQ + qq] = v.y * QSCALE;
        Qt[(x4*4+2)*PADQ + qq] = v.z * QSCALE;
        Qt[(x4*4+3)*PADQ + qq] = v.w * QSCALE;
    }

    const int g = tid >> 4;
    const int x = tid & 15;
    const int r0l = g * 4;
    const int c0l = x * 4;

    float ctx[2][4][4];
    float mrow[2][4], lrow[2][4], corr[2][4];
    #pragma unroll
    for (int a = 0; a < 2; a++)
        #pragma unroll
        for (int i = 0; i < 4; i++) {
            mrow[a][i] = -1e30f; lrow[a][i] = 0.0f;
            #pragma unroll
            for (int j = 0; j < 4; j++) ctx[a][i][j] = 0.0f;
        }

    for (int t = 0; t < Sq; t += 64) {
        __syncthreads();
        #pragma unroll
        for (int i = 0; i < 4; i++) {
            int lin = tid + i * 256;
            int kk  = lin >> 4;
            int x4  = lin & 15;
            float4 kv = *(const float4*)&Kb[(t + kk) * DKh + x4 * 4];
            Kt[(x4*4+0)*PADK + kk] = kv.x;
            Kt[(x4*4+1)*PADK + kk] = kv.y;
            Kt[(x4*4+2)*PADK + kk] = kv.z;
            Kt[(x4*4+3)*PADK + kk] = kv.w;
            float4 vv = *(const float4*)&Vb[(t + kk) * DKh + x4 * 4];
            *(float4*)&Vs[kk * PADK + x4 * 4] = vv;
        }
        __syncthreads();

        float s[2][4][4];
        #pragma unroll
        for (int a = 0; a < 2; a++)
            #pragma unroll
            for (int i = 0; i < 4; i++)
                #pragma unroll
                for (int j = 0; j < 4; j++) s[a][i][j] = 0.0f;

        #pragma unroll 8
        for (int d = 0; d < 64; d++) {
            const float* qrow = &Qt[d * PADQ];
            float4 a0 = *(const float4*)&qrow[r0l];
            float4 a1 = *(const float4*)&qrow[64 + r0l];
            float4 b0 = *(const float4*)&Kt[d * PADK + c0l];
            float af[2][4] = {{a0.x,a0.y,a0.z,a0.w},{a1.x,a1.y,a1.z,a1.w}};
            float bf[4] = {b0.x,b0.y,b0.z,b0.w};
            #pragma unroll
            for (int a = 0; a < 2; a++)
                #pragma unroll
                for (int i = 0; i < 4; i++)
                    #pragma unroll
                    for (int j = 0; j < 4; j++)
                        s[a][i][j] = fmaf(af[a][i], bf[j], s[a][i][j]);
        }

        #pragma unroll
        for (int a = 0; a < 2; a++)
            #pragma unroll
            for (int i = 0; i < 4; i++) {
                int rg = q0 + a*64 + r0l + i;
                int4 mk = *(const int4*)&mask[(size_t)rg * Sq + t + c0l];
                if (mk.x == 0) s[a][i][0] = -1e9f;
                if (mk.y == 0) s[a][i][1] = -1e9f;
                if (mk.z == 0) s[a][i][2] = -1e9f;
                if (mk.w == 0) s[a][i][3] = -1e9f;
            }

        #pragma unroll
        for (int a = 0; a < 2; a++)
            #pragma unroll
            for (int i = 0; i < 4; i++) {
                float mx = fmaxf(fmaxf(s[a][i][0], s[a][i][1]),
                                 fmaxf(s[a][i][2], s[a][i][3]));
                #pragma unroll
                for (int off = 8; off >= 1; off >>= 1)
                    mx = fmaxf(mx, __shfl_xor_sync(0xffffffffu, mx, off));
                float mn = fmaxf(mrow[a][i], mx);
                float ssum = 0.0f;
                #pragma unroll
                for (int j = 0; j < 4; j++) {
                    float e = exp2_fast(s[a][i][j] - mn);
                    s[a][i][j] = e;
                    ssum += e;
                }
                #pragma unroll
                for (int off = 8; off >= 1; off >>= 1)
                    ssum += __shfl_xor_sync(0xffffffffu, ssum, off);
                float cf = exp2_fast(mrow[a][i] - mn);
                lrow[a][i] = lrow[a][i] * cf + ssum;
                mrow[a][i] = mn;
                corr[a][i] = cf;
                *(float4*)&Ps[(a*64 + r0l + i) * PADK + c0l] =
                    make_float4(s[a][i][0], s[a][i][1], s[a][i][2], s[a][i][3]);
            }
        __syncthreads();

        #pragma unroll
        for (int a = 0; a < 2; a++)
            #pragma unroll
            for (int i = 0; i < 4; i++)
                #pragma unroll
                for (int j = 0; j < 4; j++) ctx[a][i][j] *= corr[a][i];

        #pragma unroll 4
        for (int j0 = 0; j0 < 64; j0 += 4) {
            float4 p[2][4];
            #pragma unroll
            for (int a = 0; a < 2; a++)
                #pragma unroll
                for (int i = 0; i < 4; i++)
                    p[a][i] = *(const float4*)&Ps[(a*64 + r0l + i) * PADK + j0];
            float4 v0 = *(const float4*)&Vs[(j0+0) * PADK + c0l];
            float4 v1 = *(const float4*)&Vs[(j0+1) * PADK + c0l];
            float4 v2 = *(const float4*)&Vs[(j0+2) * PADK + c0l];
            float4 v3 = *(const float4*)&Vs[(j0+3) * PADK + c0l];
            #pragma unroll
            for (int a = 0; a < 2; a++)
                #pragma unroll
                for (int i = 0; i < 4; i++) {
                    float* pp = (float*)&p[a][i];
                    float* cx = ctx[a][i];
                    cx[0] = fmaf(pp[0], v0.x, cx[0]); cx[1] = fmaf(pp[0], v0.y, cx[1]);
                    cx[2] = fmaf(pp[0], v0.z, cx[2]); cx[3] = fmaf(pp[0], v0.w, cx[3]);
                    cx[0] = fmaf(pp[1], v1.x, cx[0]); cx[1] = fmaf(pp[1], v1.y, cx[1]);
                    cx[2] = fmaf(pp[1], v1.z, cx[2]); cx[3] = fmaf(pp[1], v1.w, cx[3]);
                    cx[0] = fmaf(pp[2], v2.x, cx[0]); cx[1] = fmaf(pp[2], v2.y, cx[1]);
                    cx[2] = fmaf(pp[2], v2.z, cx[2]); cx[3] = fmaf(pp[2], v2.w, cx[3]);
                    cx[0] = fmaf(pp[3], v3.x, cx[0]); cx[1] = fmaf(pp[3], v3.y, cx[1]);
                    cx[2] = fmaf(pp[3], v3.z, cx[2]); cx[3] = fmaf(pp[3], v3.w, cx[3]);
                }
        }
    }

    #pragma unroll
    for (int a = 0; a < 2; a++)
        #pragma unroll
        for (int i = 0; i < 4; i++) {
            float inv = 1.0f / fmaxf(lrow[a][i], 1e-20f);
            int row = q0 + a*64 + r0l + i;
            float4 o;
            o.x = ctx[a][i][0] * inv; o.y = ctx[a][i][1] * inv;
            o.z = ctx[a][i][2] * inv; o.w = ctx[a][i][3] * inv;
            *(float4*)&ctxg[(size_t)(b * Sq + row) * Dm + h * DKh + c0l] = o;
        }
}

// ===========================================================================
extern "C" void kernel_launch(void* const* d_in, const int* in_sizes, int n_in,
                              void* d_out, int out_size)
{
    const float* q    = (const float*)d_in[0];
    const float* k    = (const float*)d_in[1];
    const float* v    = (const float*)d_in[2];
    const int*   mask = (const int*)  d_in[3];
    const float* Wq   = (const float*)d_in[4];
    const float* bq   = (const float*)d_in[5];
    const float* Wk   = (const float*)d_in[6];
    const float* bk   = (const float*)d_in[7];
    const float* Wv   = (const float*)d_in[8];
    const float* bv   = (const float*)d_in[9];
    const float* Wo   = (const float*)d_in[10];
    const float* bo   = (const float*)d_in[11];
    float* out = (float*)d_out;

    float *gq, *gk, *gv, *gc;
    cudaGetSymbolAddress((void**)&gq, g_Q);
    cudaGetSymbolAddress((void**)&gk, g_K);
    cudaGetSymbolAddress((void**)&gv, g_V);
    cudaGetSymbolAddress((void**)&gc, g_C);

    cudaFuncSetAttribute(mma_gemm_qkv,
                         cudaFuncAttributeMaxDynamicSharedMemorySize, GEMM_SMEM);
    cudaFuncSetAttribute(mma_gemm_o,
                         cudaFuncAttributeMaxDynamicSharedMemorySize, GEMM_SMEM);
    cudaFuncSetAttribute(attn_kernel,
                         cudaFuncAttributeMaxDynamicSharedMemorySize, ATT_SMEM);

    mma_gemm_qkv<<<dim3(8, 32, 3), 256, GEMM_SMEM>>>(
        q, k, v, Wq, Wk, Wv, bq, bk, bv, gq, gk, gv);

    attn_kernel<<<dim3(Sq / 128, Bsz * Hh), 256, ATT_SMEM>>>(gq, gk, gv, mask, gc);

    mma_gemm_o<<<dim3(8, 32), 256, GEMM_SMEM>>>(gc, Wo, bo, out);
}